// round 16
// baseline (speedup 1.0000x reference)
#include <cuda_runtime.h>

#define B_    16
#define C_    256
#define H_    56
#define W_    56
#define HW_   3136
#define MID_  64
#define OC2_  144     // KK * GROUPS = 9 * 16

// scratch for per-pixel kernels: [B][144][HW]  (~28.9 MB)
__device__ float g_weight[B_ * OC2_ * HW_];
// pre-transposed weights (filled by prep kernel each launch)
__device__ float g_w1t[C_ * MID_];        // [k][o]   : g_w1t[k*64+o] = w1[o*256+k]
__device__ float g_w2t[3 * MID_ * 48];    // [rr][k][lr], lr=msl*6+ii -> o2=msl*18+rr*6+ii

// ---- packed f32x2 helpers ------------------------------------------------
typedef unsigned long long ull;

__device__ __forceinline__ ull pack2(float lo, float hi) {
    ull r;
    asm("mov.b64 %0, {%1, %2};" : "=l"(r) : "f"(lo), "f"(hi));
    return r;
}
__device__ __forceinline__ void unpack2(ull v, float& lo, float& hi) {
    asm("mov.b64 {%0, %1}, %2;" : "=f"(lo), "=f"(hi) : "l"(v));
}
__device__ __forceinline__ void ffma2(ull& d, ull a, ull b) {
    asm("fma.rn.f32x2 %0, %1, %2, %0;" : "+l"(d) : "l"(a), "l"(b));
}

union F4U2 { float4 f; ull u[2]; };
union F2U1 { float2 f; ull u; };

// ---- cp.async helpers ----------------------------------------------------
__device__ __forceinline__ void cp16(void* smem, const void* gmem) {
    unsigned sa = (unsigned)__cvta_generic_to_shared(smem);
    asm volatile("cp.async.ca.shared.global [%0], [%1], 16;" :: "r"(sa), "l"(gmem));
}
__device__ __forceinline__ void cp_commit() {
    asm volatile("cp.async.commit_group;");
}
template <int N> __device__ __forceinline__ void cp_wait() {
    asm volatile("cp.async.wait_group %0;" :: "n"(N));
}

// ---------------------------------------------------------------------------
// Prep: transpose w1 -> g_w1t[k][o]; permute w2 -> g_w2t[rr][k][lr]
// ---------------------------------------------------------------------------
__global__ void prep_kernel(const float* __restrict__ w1,
                            const float* __restrict__ w2)
{
    int idx = blockIdx.x * 256 + threadIdx.x;
    if (idx < C_ * MID_) {
        int k = idx >> 6, o = idx & 63;
        g_w1t[k * MID_ + o] = w1[o * C_ + k];
    }
    if (idx < 3 * MID_ * 48) {
        int rr  = idx / (MID_ * 48);
        int rem = idx - rr * (MID_ * 48);
        int k   = rem / 48, lr = rem - (rem / 48) * 48;
        int msl = lr / 6, ii = lr - msl * 6;
        int o2  = msl * 18 + rr * 6 + ii;
        g_w2t[idx] = w2[o2 * MID_ + k];
    }
}

// ---------------------------------------------------------------------------
// Kernel 1: fused conv1(1x1)+BN+ReLU+conv2(1x1)+bias — R14 verbatim.
// cp.async 2-stage pipeline, 128 threads, 64 px/block, smem 32 KB.
// ---------------------------------------------------------------------------
__global__ __launch_bounds__(128) void fused_conv_kernel(
    const float* __restrict__ x,
    const float* __restrict__ bn_gamma,
    const float* __restrict__ bn_beta,
    const float* __restrict__ bn_mean,
    const float* __restrict__ bn_var,
    const float* __restrict__ b2)
{
    __shared__ __align__(16) float buf[8192];   // 32 KB

    const int tid = threadIdx.x;
    const int blk = blockIdx.x;
    const int b   = blk / 49;
    const int hw0 = (blk % 49) * 64;

    const float* xb = x + (size_t)b * C_ * HW_ + hw0;

    const int ps  = tid & 15;
    const int px0 = ps * 4;
    const int ms  = tid >> 4;                  // mid-slot 0..7

    ull accp[8][2];
    #pragma unroll
    for (int i = 0; i < 8; i++) { accp[i][0] = 0ull; accp[i][1] = 0ull; }

    // ---- prefetch chunk 0 ----
    {
        float* As = buf;  float* Bs = buf + 2048;
        #pragma unroll
        for (int j = 0; j < 4; j++) {
            int off = (tid + 128 * j) * 4;
            cp16(As + off, g_w1t + off);
        }
        #pragma unroll
        for (int j = 0; j < 4; j++) {
            int f4i = tid + 128 * j;
            int kc  = f4i >> 4, p4 = (f4i & 15) * 4;
            cp16(Bs + kc * 64 + p4, xb + (size_t)kc * HW_ + p4);
        }
        cp_commit();
    }

    for (int c = 0; c < 8; c++) {
        if (c < 7) {
            int sb = (c + 1) & 1;
            float* As = buf + sb * 4096;
            float* Bs = As + 2048;
            const float* w1c = g_w1t + (c + 1) * 2048;
            int ktn = (c + 1) * 32;
            #pragma unroll
            for (int j = 0; j < 4; j++) {
                int off = (tid + 128 * j) * 4;
                cp16(As + off, w1c + off);
            }
            #pragma unroll
            for (int j = 0; j < 4; j++) {
                int f4i = tid + 128 * j;
                int kc  = f4i >> 4, p4 = (f4i & 15) * 4;
                cp16(Bs + kc * 64 + p4, xb + (size_t)(ktn + kc) * HW_ + p4);
            }
            cp_commit();
            cp_wait<1>();
        } else {
            cp_wait<0>();
        }
        __syncthreads();

        const float* As = buf + (c & 1) * 4096;
        const float* Bs = As + 2048;

        #pragma unroll 8
        for (int kc = 0; kc < 32; kc++) {
            F4U2 B0;
            B0.f = *(const float4*)&Bs[kc * 64 + px0];
            ull tp0 = B0.u[0], tp1 = B0.u[1];
            float4 a0 = *(const float4*)&As[kc * 64 + ms * 8];
            float4 a1 = *(const float4*)&As[kc * 64 + ms * 8 + 4];
            float av[8] = {a0.x, a0.y, a0.z, a0.w, a1.x, a1.y, a1.z, a1.w};
            #pragma unroll
            for (int i = 0; i < 8; i++) {
                ull ap = pack2(av[i], av[i]);
                ffma2(accp[i][0], ap, tp0);
                ffma2(accp[i][1], ap, tp1);
            }
        }
        __syncthreads();
    }

    // BN (eval) + ReLU epilogue -> Ts
    float (*Ts)[64] = (float(*)[64])buf;
    #pragma unroll
    for (int i = 0; i < 8; i++) {
        int o = ms * 8 + i;
        float s  = bn_gamma[o] * rsqrtf(bn_var[o] + 1e-5f);
        float sh = bn_beta[o] - bn_mean[o] * s;
        float lo0, hi0, lo1, hi1;
        unpack2(accp[i][0], lo0, hi0);
        unpack2(accp[i][1], lo1, hi1);
        float4 t;
        t.x = fmaxf(fmaf(lo0, s, sh), 0.f);
        t.y = fmaxf(fmaf(hi0, s, sh), 0.f);
        t.z = fmaxf(fmaf(lo1, s, sh), 0.f);
        t.w = fmaxf(fmaf(hi1, s, sh), 0.f);
        *(float4*)&Ts[o][px0] = t;
    }
    __syncthreads();

    // Stage 2: three passes over 48 output rows each
    float* W2s = buf + 4096;                   // [64][48]
    const int os = ms;

    for (int rr = 0; rr < 3; rr++) {
        const float4* src = (const float4*)(g_w2t + rr * (MID_ * 48));
        #pragma unroll
        for (int j = 0; j < 6; j++) {
            int i4 = tid + 128 * j;            // 0..767
            ((float4*)W2s)[i4] = src[i4];
        }
        __syncthreads();

        ull accq[6][2];
        #pragma unroll
        for (int q = 0; q < 6; q++) { accq[q][0] = 0ull; accq[q][1] = 0ull; }

        #pragma unroll 8
        for (int k = 0; k < MID_; k++) {
            F4U2 T0;
            T0.f = *(const float4*)&Ts[k][px0];
            ull tp0 = T0.u[0], tp1 = T0.u[1];
            const float* wk = W2s + k * 48 + os * 6;
            float2 w01 = *(const float2*)(wk);
            float2 w23 = *(const float2*)(wk + 2);
            float2 w45 = *(const float2*)(wk + 4);
            float wv[6] = {w01.x, w01.y, w23.x, w23.y, w45.x, w45.y};
            #pragma unroll
            for (int ii = 0; ii < 6; ii++) {
                ull wp = pack2(wv[ii], wv[ii]);
                ffma2(accq[ii][0], wp, tp0);
                ffma2(accq[ii][1], wp, tp1);
            }
        }

        #pragma unroll
        for (int ii = 0; ii < 6; ii++) {
            int o2 = os * 18 + rr * 6 + ii;
            float bias = b2[o2];
            float lo0, hi0, lo1, hi1;
            unpack2(accq[ii][0], lo0, hi0);
            unpack2(accq[ii][1], lo1, hi1);
            float4 o4 = {lo0 + bias, hi0 + bias, lo1 + bias, hi1 + bias};
            *(float4*)&g_weight[((size_t)b * OC2_ + o2) * HW_ + hw0 + px0] = o4;
        }
        __syncthreads();
    }
}

// ---------------------------------------------------------------------------
// Kernel 2: involution — R14 structure + f32x2 packed inner loop.
// Block = (4-row tile, group g, b). 256 threads:
// gs = tid>>4 (channel 0..15), slot = tid&15 (col quad, 14 active).
// Accumulator pairs (a0,a1),(a2,a3); 4 of 6 x-pairs come free from the
// float4/float2 LDS registers, only 2 packs per (dr). 18 FFMA2 + 6 packs
// per row vs 36 FMA before; LDS unchanged.
// ---------------------------------------------------------------------------
__global__ __launch_bounds__(256) void involution_kernel(
    const float* __restrict__ x,
    float* __restrict__ out)
{
    __shared__ float ws[9][224];      // [kk][r*56+col]                8.1 KB
    __shared__ float xs[6][16][60];   // [y0-1..y0+4][ch][col -1..58] 23.0 KB

    const int y0  = blockIdx.x * 4;
    const int g   = blockIdx.y;
    const int b   = blockIdx.z;
    const int tid = threadIdx.x;
    const int warp = tid >> 5, lane = tid & 31;

    const float* xsrc = x + ((size_t)(b * C_ + g * 16)) * HW_;
    for (int seg = warp; seg < 96; seg += 8) {
        int row = seg >> 4, c = seg & 15;
        int gy = y0 + row - 1;
        bool rowok = ((unsigned)gy < (unsigned)H_);
        const float* src = xsrc + (size_t)c * HW_ + gy * W_;
        #pragma unroll
        for (int q = 0; q < 2; q++) {
            int col = lane + q * 32;
            if (col < 60) {
                int gx = col - 1;
                float v = 0.f;
                if (rowok && (unsigned)gx < (unsigned)W_) v = src[gx];
                xs[row][c][col] = v;
            }
        }
    }
    const float* wsrc = g_weight + ((size_t)(b * OC2_ + g * 9)) * HW_ + y0 * W_;
    for (int kk = warp; kk < 9; kk += 8) {
        #pragma unroll
        for (int q = 0; q < 7; q++) {
            int col = lane + q * 32;
            ws[kk][col] = wsrc[(size_t)kk * HW_ + col];
        }
    }
    __syncthreads();

    const int gs   = tid >> 4;
    const int slot = tid & 15;
    if (slot >= 14) return;
    const int x0 = slot * 4;

    float* outp = out + ((size_t)(b * C_ + g * 16 + gs)) * HW_ + y0 * W_ + x0;

    #pragma unroll
    for (int r = 0; r < 4; r++) {
        ull A01 = 0ull, A23 = 0ull;
        const int wb = r * 56 + x0;
        #pragma unroll
        for (int dr = 0; dr < 3; dr++) {
            const float* xr = &xs[r + dr][gs][x0];
            F4U2 V4; V4.f = *(const float4*)xr;        // u[0]=(x0,x1) u[1]=(x2,x3)
            F2U1 V2; V2.f = *(const float2*)(xr + 4);  // u  =(x4,x5)
            ull p12 = pack2(V4.f.y, V4.f.z);           // (x1,x2)
            ull p34 = pack2(V4.f.w, V2.f.x);           // (x3,x4)

            F4U2 W0; W0.f = *(const float4*)&ws[dr * 3 + 0][wb];
            ffma2(A01, W0.u[0], V4.u[0]);
            ffma2(A23, W0.u[1], V4.u[1]);

            F4U2 W1; W1.f = *(const float4*)&ws[dr * 3 + 1][wb];
            ffma2(A01, W1.u[0], p12);
            ffma2(A23, W1.u[1], p34);

            F4U2 W2; W2.f = *(const float4*)&ws[dr * 3 + 2][wb];
            ffma2(A01, W2.u[0], V4.u[1]);
            ffma2(A23, W2.u[1], V2.u);
        }
        float a0, a1, a2, a3;
        unpack2(A01, a0, a1);
        unpack2(A23, a2, a3);
        *(float4*)&outp[r * W_] = make_float4(a0, a1, a2, a3);
    }
}

extern "C" void kernel_launch(void* const* d_in, const int* in_sizes, int n_in,
                              void* d_out, int out_size)
{
    const float* x        = (const float*)d_in[0];
    const float* w1       = (const float*)d_in[1];
    const float* bn_gamma = (const float*)d_in[2];
    const float* bn_beta  = (const float*)d_in[3];
    const float* bn_mean  = (const float*)d_in[4];
    const float* bn_var   = (const float*)d_in[5];
    const float* w2       = (const float*)d_in[6];
    const float* b2       = (const float*)d_in[7];
    float* out = (float*)d_out;

    prep_kernel<<<64, 256>>>(w1, w2);

    fused_conv_kernel<<<B_ * 49, 128>>>(
        x, bn_gamma, bn_beta, bn_mean, bn_var, b2);

    involution_kernel<<<dim3(14, 16, 16), 256>>>(x, out);
}

// round 17
// speedup vs baseline: 1.4847x; 1.4847x over previous
#include <cuda_runtime.h>

#define B_    16
#define C_    256
#define H_    56
#define W_    56
#define HW_   3136
#define MID_  64
#define OC2_  144     // KK * GROUPS = 9 * 16

// scratch for per-pixel kernels: [B][144][HW]  (~28.9 MB)
__device__ float g_weight[B_ * OC2_ * HW_];
// pre-transposed weights (filled by prep kernel each launch)
__device__ float g_w1t[C_ * MID_];        // [k][o]   : g_w1t[k*64+o] = w1[o*256+k]
__device__ float g_w2t[3 * MID_ * 48];    // [rr][k][lr], lr=msl*6+ii -> o2=msl*18+rr*6+ii

// ---- packed f32x2 helpers ------------------------------------------------
typedef unsigned long long ull;

__device__ __forceinline__ ull pack2(float lo, float hi) {
    ull r;
    asm("mov.b64 %0, {%1, %2};" : "=l"(r) : "f"(lo), "f"(hi));
    return r;
}
__device__ __forceinline__ void unpack2(ull v, float& lo, float& hi) {
    asm("mov.b64 {%0, %1}, %2;" : "=f"(lo), "=f"(hi) : "l"(v));
}
__device__ __forceinline__ void ffma2(ull& d, ull a, ull b) {
    asm("fma.rn.f32x2 %0, %1, %2, %0;" : "+l"(d) : "l"(a), "l"(b));
}

union F4U2 { float4 f; ull u[2]; };

// ---- cp.async helpers ----------------------------------------------------
__device__ __forceinline__ void cp16(void* smem, const void* gmem) {
    unsigned sa = (unsigned)__cvta_generic_to_shared(smem);
    asm volatile("cp.async.ca.shared.global [%0], [%1], 16;" :: "r"(sa), "l"(gmem));
}
__device__ __forceinline__ void cp_commit() {
    asm volatile("cp.async.commit_group;");
}
template <int N> __device__ __forceinline__ void cp_wait() {
    asm volatile("cp.async.wait_group %0;" :: "n"(N));
}

// ---------------------------------------------------------------------------
// Prep: transpose w1 -> g_w1t[k][o]; permute w2 -> g_w2t[rr][k][lr]
// ---------------------------------------------------------------------------
__global__ void prep_kernel(const float* __restrict__ w1,
                            const float* __restrict__ w2)
{
    int idx = blockIdx.x * 256 + threadIdx.x;
    if (idx < C_ * MID_) {
        int k = idx >> 6, o = idx & 63;
        g_w1t[k * MID_ + o] = w1[o * C_ + k];
    }
    if (idx < 3 * MID_ * 48) {
        int rr  = idx / (MID_ * 48);
        int rem = idx - rr * (MID_ * 48);
        int k   = rem / 48, lr = rem - (rem / 48) * 48;
        int msl = lr / 6, ii = lr - msl * 6;
        int o2  = msl * 18 + rr * 6 + ii;
        g_w2t[idx] = w2[o2 * MID_ + k];
    }
}

// ---------------------------------------------------------------------------
// Kernel 1: fused conv1(1x1)+BN+ReLU+conv2(1x1)+bias.
// cp.async 2-stage double-buffered pipeline, 128 threads, 64 px/block,
// smem 32 KB -> 7 blocks/SM.
// Stage 1: t[64][64px]  = w1^T tiles * x tiles      (8mid x 4px, FFMA2)
// Stage 2: w [144][64px]= w2 * t + b2               (6o2 x 4px, 3 passes)
// ---------------------------------------------------------------------------
__global__ __launch_bounds__(128) void fused_conv_kernel(
    const float* __restrict__ x,
    const float* __restrict__ bn_gamma,
    const float* __restrict__ bn_beta,
    const float* __restrict__ bn_mean,
    const float* __restrict__ bn_var,
    const float* __restrict__ b2)
{
    __shared__ __align__(16) float buf[8192];   // 32 KB

    const int tid = threadIdx.x;
    const int blk = blockIdx.x;
    const int b   = blk / 49;
    const int hw0 = (blk % 49) * 64;

    const float* xb = x + (size_t)b * C_ * HW_ + hw0;

    const int ps  = tid & 15;
    const int px0 = ps * 4;
    const int ms  = tid >> 4;                  // mid-slot 0..7

    ull accp[8][2];
    #pragma unroll
    for (int i = 0; i < 8; i++) { accp[i][0] = 0ull; accp[i][1] = 0ull; }

    // ---- prefetch chunk 0 ----
    {
        float* As = buf;  float* Bs = buf + 2048;
        #pragma unroll
        for (int j = 0; j < 4; j++) {
            int off = (tid + 128 * j) * 4;
            cp16(As + off, g_w1t + off);
        }
        #pragma unroll
        for (int j = 0; j < 4; j++) {
            int f4i = tid + 128 * j;
            int kc  = f4i >> 4, p4 = (f4i & 15) * 4;
            cp16(Bs + kc * 64 + p4, xb + (size_t)kc * HW_ + p4);
        }
        cp_commit();
    }

    for (int c = 0; c < 8; c++) {
        if (c < 7) {
            int sb = (c + 1) & 1;
            float* As = buf + sb * 4096;
            float* Bs = As + 2048;
            const float* w1c = g_w1t + (c + 1) * 2048;
            int ktn = (c + 1) * 32;
            #pragma unroll
            for (int j = 0; j < 4; j++) {
                int off = (tid + 128 * j) * 4;
                cp16(As + off, w1c + off);
            }
            #pragma unroll
            for (int j = 0; j < 4; j++) {
                int f4i = tid + 128 * j;
                int kc  = f4i >> 4, p4 = (f4i & 15) * 4;
                cp16(Bs + kc * 64 + p4, xb + (size_t)(ktn + kc) * HW_ + p4);
            }
            cp_commit();
            cp_wait<1>();
        } else {
            cp_wait<0>();
        }
        __syncthreads();

        const float* As = buf + (c & 1) * 4096;
        const float* Bs = As + 2048;

        #pragma unroll 8
        for (int kc = 0; kc < 32; kc++) {
            F4U2 B0;
            B0.f = *(const float4*)&Bs[kc * 64 + px0];
            ull tp0 = B0.u[0], tp1 = B0.u[1];
            float4 a0 = *(const float4*)&As[kc * 64 + ms * 8];
            float4 a1 = *(const float4*)&As[kc * 64 + ms * 8 + 4];
            float av[8] = {a0.x, a0.y, a0.z, a0.w, a1.x, a1.y, a1.z, a1.w};
            #pragma unroll
            for (int i = 0; i < 8; i++) {
                ull ap = pack2(av[i], av[i]);
                ffma2(accp[i][0], ap, tp0);
                ffma2(accp[i][1], ap, tp1);
            }
        }
        __syncthreads();
    }

    // BN (eval) + ReLU epilogue -> Ts
    float (*Ts)[64] = (float(*)[64])buf;
    #pragma unroll
    for (int i = 0; i < 8; i++) {
        int o = ms * 8 + i;
        float s  = bn_gamma[o] * rsqrtf(bn_var[o] + 1e-5f);
        float sh = bn_beta[o] - bn_mean[o] * s;
        float lo0, hi0, lo1, hi1;
        unpack2(accp[i][0], lo0, hi0);
        unpack2(accp[i][1], lo1, hi1);
        float4 t;
        t.x = fmaxf(fmaf(lo0, s, sh), 0.f);
        t.y = fmaxf(fmaf(hi0, s, sh), 0.f);
        t.z = fmaxf(fmaf(lo1, s, sh), 0.f);
        t.w = fmaxf(fmaf(hi1, s, sh), 0.f);
        *(float4*)&Ts[o][px0] = t;
    }
    __syncthreads();

    // Stage 2: three passes over 48 output rows each
    float* W2s = buf + 4096;                   // [64][48]
    const int os = ms;

    for (int rr = 0; rr < 3; rr++) {
        const float4* src = (const float4*)(g_w2t + rr * (MID_ * 48));
        #pragma unroll
        for (int j = 0; j < 6; j++) {
            int i4 = tid + 128 * j;            // 0..767
            ((float4*)W2s)[i4] = src[i4];
        }
        __syncthreads();

        ull accq[6][2];
        #pragma unroll
        for (int q = 0; q < 6; q++) { accq[q][0] = 0ull; accq[q][1] = 0ull; }

        #pragma unroll 8
        for (int k = 0; k < MID_; k++) {
            F4U2 T0;
            T0.f = *(const float4*)&Ts[k][px0];
            ull tp0 = T0.u[0], tp1 = T0.u[1];
            const float* wk = W2s + k * 48 + os * 6;
            float2 w01 = *(const float2*)(wk);
            float2 w23 = *(const float2*)(wk + 2);
            float2 w45 = *(const float2*)(wk + 4);
            float wv[6] = {w01.x, w01.y, w23.x, w23.y, w45.x, w45.y};
            #pragma unroll
            for (int ii = 0; ii < 6; ii++) {
                ull wp = pack2(wv[ii], wv[ii]);
                ffma2(accq[ii][0], wp, tp0);
                ffma2(accq[ii][1], wp, tp1);
            }
        }

        #pragma unroll
        for (int ii = 0; ii < 6; ii++) {
            int o2 = os * 18 + rr * 6 + ii;
            float bias = b2[o2];
            float lo0, hi0, lo1, hi1;
            unpack2(accq[ii][0], lo0, hi0);
            unpack2(accq[ii][1], lo1, hi1);
            float4 o4 = {lo0 + bias, hi0 + bias, lo1 + bias, hi1 + bias};
            *(float4*)&g_weight[((size_t)b * OC2_ + o2) * HW_ + hw0 + px0] = o4;
        }
        __syncthreads();
    }
}

// ---------------------------------------------------------------------------
// Kernel 2: involution — best measured configuration (R7/R14): smem-staged
// weights, scalar FMA with 4 independent accumulator chains per row.
// Block = (4-row tile, group g, b). 256 threads:
// gs = tid>>4 (channel 0..15), slot = tid&15 (col quad, 14 active).
// ---------------------------------------------------------------------------
__global__ __launch_bounds__(256) void involution_kernel(
    const float* __restrict__ x,
    float* __restrict__ out)
{
    __shared__ float ws[9][224];      // [kk][r*56+col]                8.1 KB
    __shared__ float xs[6][16][60];   // [y0-1..y0+4][ch][col -1..58] 23.0 KB

    const int y0  = blockIdx.x * 4;
    const int g   = blockIdx.y;
    const int b   = blockIdx.z;
    const int tid = threadIdx.x;
    const int warp = tid >> 5, lane = tid & 31;

    const float* xsrc = x + ((size_t)(b * C_ + g * 16)) * HW_;
    for (int seg = warp; seg < 96; seg += 8) {
        int row = seg >> 4, c = seg & 15;
        int gy = y0 + row - 1;
        bool rowok = ((unsigned)gy < (unsigned)H_);
        const float* src = xsrc + (size_t)c * HW_ + gy * W_;
        #pragma unroll
        for (int q = 0; q < 2; q++) {
            int col = lane + q * 32;
            if (col < 60) {
                int gx = col - 1;
                float v = 0.f;
                if (rowok && (unsigned)gx < (unsigned)W_) v = src[gx];
                xs[row][c][col] = v;
            }
        }
    }
    const float* wsrc = g_weight + ((size_t)(b * OC2_ + g * 9)) * HW_ + y0 * W_;
    for (int kk = warp; kk < 9; kk += 8) {
        #pragma unroll
        for (int q = 0; q < 7; q++) {
            int col = lane + q * 32;
            ws[kk][col] = wsrc[(size_t)kk * HW_ + col];
        }
    }
    __syncthreads();

    const int gs   = tid >> 4;
    const int slot = tid & 15;
    if (slot >= 14) return;
    const int x0 = slot * 4;

    float* outp = out + ((size_t)(b * C_ + g * 16 + gs)) * HW_ + y0 * W_ + x0;

    #pragma unroll
    for (int r = 0; r < 4; r++) {
        float a0 = 0.f, a1 = 0.f, a2 = 0.f, a3 = 0.f;
        const int wb = r * 56 + x0;
        #pragma unroll
        for (int dr = 0; dr < 3; dr++) {
            const float* xr = &xs[r + dr][gs][x0];
            float4 v4 = *(const float4*)xr;
            float2 v2 = *(const float2*)(xr + 4);

            float4 w0 = *(const float4*)&ws[dr * 3 + 0][wb];
            a0 = fmaf(w0.x, v4.x, a0);
            a1 = fmaf(w0.y, v4.y, a1);
            a2 = fmaf(w0.z, v4.z, a2);
            a3 = fmaf(w0.w, v4.w, a3);

            float4 w1_ = *(const float4*)&ws[dr * 3 + 1][wb];
            a0 = fmaf(w1_.x, v4.y, a0);
            a1 = fmaf(w1_.y, v4.z, a1);
            a2 = fmaf(w1_.z, v4.w, a2);
            a3 = fmaf(w1_.w, v2.x, a3);

            float4 w2_ = *(const float4*)&ws[dr * 3 + 2][wb];
            a0 = fmaf(w2_.x, v4.z, a0);
            a1 = fmaf(w2_.y, v4.w, a1);
            a2 = fmaf(w2_.z, v2.x, a2);
            a3 = fmaf(w2_.w, v2.y, a3);
        }
        *(float4*)&outp[r * W_] = make_float4(a0, a1, a2, a3);
    }
}

extern "C" void kernel_launch(void* const* d_in, const int* in_sizes, int n_in,
                              void* d_out, int out_size)
{
    const float* x        = (const float*)d_in[0];
    const float* w1       = (const float*)d_in[1];
    const float* bn_gamma = (const float*)d_in[2];
    const float* bn_beta  = (const float*)d_in[3];
    const float* bn_mean  = (const float*)d_in[4];
    const float* bn_var   = (const float*)d_in[5];
    const float* w2       = (const float*)d_in[6];
    const float* b2       = (const float*)d_in[7];
    float* out = (float*)d_out;

    prep_kernel<<<64, 256>>>(w1, w2);

    fused_conv_kernel<<<B_ * 49, 128>>>(
        x, bn_gamma, bn_beta, bn_mean, bn_var, b2);

    involution_kernel<<<dim3(14, 16, 16), 256>>>(x, out);
}